// round 3
// baseline (speedup 1.0000x reference)
#include <cuda_runtime.h>
#include <cuda_bf16.h>

// N=4096, A=256, D_IN=39, H=50, S=8
#define NROWS  4096
#define NATOM  256
#define DIN    39
#define HDIM   50

#define TILE_N 128
#define NT     128            // threads per block: 16 ty x 8 tx
#define RPP    4              // row-PAIRS per thread (8 rows)
#define CPT    7              // cols per thread (8*7 = 56 >= 50)
#define XPP    82             // floats per row-pair in X2  (ty-stride 4*82=328 ≡ 8 mod 32 banks)
#define HPP    114            // floats per row-pair in H   (ty-stride 4*114=456 ≡ 8 mod 32 banks)
#define WPD    112            // duplicated weight row pitch (2*56 floats)

// Shared memory layout (floats):
//  Union region U (phase1: X2[64*82]=5248 + W1d[39*112]=4368 = 9616 floats;
//                  phase2: H[64*114]=7296 floats aliases it after a sync)
//  W2d[50*112]=5600, b1d[112], b2d[112], w3d[112], b3s[4]
#define OFF_X2   0
#define OFF_W1D  5248
#define OFF_H    0
#define OFF_W2D  9616
#define OFF_B1D  (OFF_W2D + 5600)       // 15216
#define OFF_B2D  (OFF_B1D + 112)
#define OFF_W3D  (OFF_B2D + 112)
#define OFF_B3   (OFF_W3D + 112)
#define SMEM_FLOATS (OFF_B3 + 4)        // 15556 floats
#define SMEM_BYTES  (SMEM_FLOATS * 4)   // 62224 bytes -> 3 CTAs/SM

typedef unsigned long long u64;

__device__ __forceinline__ void fma2(u64& d, u64 a, u64 b) {
    // d = a*b + d per fp32 lane; bit-exact vs 2x scalar fmaf.
    asm("fma.rn.f32x2 %0, %1, %2, %0;" : "+l"(d) : "l"(a), "l"(b));
}
__device__ __forceinline__ void add2(u64& d, u64 a, u64 b) {
    asm("add.rn.f32x2 %0, %1, %2;" : "=l"(d) : "l"(a), "l"(b));
}
__device__ __forceinline__ float2 unpack2(u64 v) {
    float2 r;
    asm("mov.b64 {%0, %1}, %2;" : "=f"(r.x), "=f"(r.y) : "l"(v));
    return r;
}
__device__ __forceinline__ u64 pack2(float lo, float hi) {
    u64 r;
    asm("mov.b64 %0, {%1, %2};" : "=l"(r) : "f"(lo), "f"(hi));
    return r;
}
__device__ __forceinline__ float silu_f(float x) {
    return x / (1.0f + __expf(-x));
}

__global__ __launch_bounds__(NT)
void atomic_mlp_kernel(const float* __restrict__ desc,
                       const int*   __restrict__ numbers,
                       const float* __restrict__ W1,
                       const float* __restrict__ b1,
                       const float* __restrict__ W2,
                       const float* __restrict__ b2,
                       const float* __restrict__ W3,
                       const float* __restrict__ b3,
                       float* __restrict__ out)
{
    extern __shared__ float sm[];

    const int a   = blockIdx.y;
    const int n0  = blockIdx.x * TILE_N;
    const int tid = threadIdx.x;
    const int s   = numbers[a];

    // ---- Stage X2: pair-interleaved desc tile: (r,k) -> (r>>1)*XPP + 2k + (r&1) ----
    {
        const float* Xg = desc + ((size_t)n0 * NATOM + a) * DIN;
        #pragma unroll 4
        for (int i = tid; i < TILE_N * DIN; i += NT) {
            int r = i / DIN, k = i - r * DIN;
            sm[OFF_X2 + (r >> 1) * XPP + 2 * k + (r & 1)] =
                Xg[(size_t)r * (NATOM * DIN) + k];
        }
    }
    // ---- Stage duplicated weights: W[k][j] -> (w,w) at k*WPD + 2j ----
    {
        const float* W1g = W1 + s * (DIN * HDIM);
        #pragma unroll 4
        for (int i = tid; i < DIN * HDIM; i += NT) {
            int k = i / HDIM, j = i - k * HDIM;
            float v = W1g[i];
            *(float2*)&sm[OFF_W1D + k * WPD + 2 * j] = make_float2(v, v);
        }
        const float* W2g = W2 + s * (HDIM * HDIM);
        #pragma unroll 4
        for (int i = tid; i < HDIM * HDIM; i += NT) {
            int k = i / HDIM, j = i - k * HDIM;
            float v = W2g[i];
            *(float2*)&sm[OFF_W2D + k * WPD + 2 * j] = make_float2(v, v);
        }
        if (tid < 56) {
            float v1 = 0.f, v2 = 0.f, v3 = 0.f;
            if (tid < HDIM) {
                v1 = b1[s * HDIM + tid];
                v2 = b2[s * HDIM + tid];
                v3 = W3[s * HDIM + tid];
            }
            *(float2*)&sm[OFF_B1D + 2 * tid] = make_float2(v1, v1);
            *(float2*)&sm[OFF_B2D + 2 * tid] = make_float2(v2, v2);
            *(float2*)&sm[OFF_W3D + 2 * tid] = make_float2(v3, v3);
        }
        if (tid == 0) sm[OFF_B3] = b3[s];
    }
    __syncthreads();

    const int ty = tid >> 3;             // 0..15
    const int tx = tid & 7;              // 0..7
    const int prow = ty * RPP;           // first pair index (covers rows 8ty..8ty+7)
    const int col0 = tx * CPT;           // 0..49

    u64 acc[RPP][CPT];

    // ================= Layer 1: acc = X @ W1 (f32x2 over row pairs) =================
    #pragma unroll
    for (int p = 0; p < RPP; ++p)
        #pragma unroll
        for (int j = 0; j < CPT; ++j) acc[p][j] = 0ull;

    #pragma unroll
    for (int k = 0; k < DIN; ++k) {
        u64 av[RPP], bv[CPT];
        #pragma unroll
        for (int p = 0; p < RPP; ++p)
            av[p] = *(const u64*)&sm[OFF_X2 + (prow + p) * XPP + 2 * k];
        #pragma unroll
        for (int j = 0; j < CPT; ++j)
            bv[j] = *(const u64*)&sm[OFF_W1D + k * WPD + 2 * (col0 + j)];
        #pragma unroll
        for (int p = 0; p < RPP; ++p)
            #pragma unroll
            for (int j = 0; j < CPT; ++j)
                fma2(acc[p][j], av[p], bv[j]);
    }

    __syncthreads();   // all X2/W1d reads done before H aliases the region

    // bias + silu + store H pair-interleaved
    #pragma unroll
    for (int p = 0; p < RPP; ++p) {
        #pragma unroll
        for (int j = 0; j < CPT; ++j) {
            float2 v = unpack2(acc[p][j]);
            float2 b = *(const float2*)&sm[OFF_B1D + 2 * (col0 + j)];
            v.x = silu_f(v.x + b.x);
            v.y = silu_f(v.y + b.y);
            *(float2*)&sm[OFF_H + (prow + p) * HPP + 2 * (col0 + j)] = v;
        }
    }
    __syncthreads();

    // ================= Layer 2: acc = H @ W2 =================
    #pragma unroll
    for (int p = 0; p < RPP; ++p)
        #pragma unroll
        for (int j = 0; j < CPT; ++j) acc[p][j] = 0ull;

    #pragma unroll
    for (int k = 0; k < HDIM; ++k) {
        u64 av[RPP], bv[CPT];
        #pragma unroll
        for (int p = 0; p < RPP; ++p)
            av[p] = *(const u64*)&sm[OFF_H + (prow + p) * HPP + 2 * k];
        #pragma unroll
        for (int j = 0; j < CPT; ++j)
            bv[j] = *(const u64*)&sm[OFF_W2D + k * WPD + 2 * (col0 + j)];
        #pragma unroll
        for (int p = 0; p < RPP; ++p)
            #pragma unroll
            for (int j = 0; j < CPT; ++j)
                fma2(acc[p][j], av[p], bv[j]);
    }

    // ======== Layer 3 in registers: silu(acc+b2) . w3, packed partial dot ========
    u64 ps[RPP];
    #pragma unroll
    for (int p = 0; p < RPP; ++p) ps[p] = 0ull;

    #pragma unroll
    for (int j = 0; j < CPT; ++j) {
        if (col0 + j < HDIM) {                      // guard padded cols (garbage weights)
            u64 w3p = *(const u64*)&sm[OFF_W3D + 2 * (col0 + j)];
            float2 b = *(const float2*)&sm[OFF_B2D + 2 * (col0 + j)];
            #pragma unroll
            for (int p = 0; p < RPP; ++p) {
                float2 v = unpack2(acc[p][j]);
                v.x = silu_f(v.x + b.x);
                v.y = silu_f(v.y + b.y);
                fma2(ps[p], pack2(v.x, v.y), w3p);
            }
        }
    }

    // Reduce across the 8 tx lanes (lanes (ty%4)*8 + tx within the warp)
    #pragma unroll
    for (int m = 1; m < 8; m <<= 1) {
        #pragma unroll
        for (int p = 0; p < RPP; ++p) {
            u64 o = __shfl_xor_sync(0xffffffffu, ps[p], m);
            add2(ps[p], ps[p], o);
        }
    }

    if (tx == 0) {
        float b3v = sm[OFF_B3];
        #pragma unroll
        for (int p = 0; p < RPP; ++p) {
            float2 v = unpack2(ps[p]);
            int row = ty * 8 + 2 * p;               // pair (prow+p) covers rows row, row+1
            out[(size_t)(n0 + row) * NATOM + a]     = v.x + b3v;
            out[(size_t)(n0 + row + 1) * NATOM + a] = v.y + b3v;
        }
    }
}

extern "C" void kernel_launch(void* const* d_in, const int* in_sizes, int n_in,
                              void* d_out, int out_size)
{
    const float* desc    = (const float*)d_in[0];
    const int*   numbers = (const int*)  d_in[1];
    const float* W1      = (const float*)d_in[2];
    const float* b1      = (const float*)d_in[3];
    const float* W2      = (const float*)d_in[4];
    const float* b2      = (const float*)d_in[5];
    const float* W3      = (const float*)d_in[6];
    const float* b3      = (const float*)d_in[7];
    float* out = (float*)d_out;

    cudaFuncSetAttribute(atomic_mlp_kernel,
                         cudaFuncAttributeMaxDynamicSharedMemorySize, SMEM_BYTES);

    dim3 grid(NROWS / TILE_N, NATOM);
    atomic_mlp_kernel<<<grid, NT, SMEM_BYTES>>>(
        desc, numbers, W1, b1, W2, b2, W3, b3, out);
}